// round 3
// baseline (speedup 1.0000x reference)
#include <cuda_runtime.h>
#include <math.h>

#define N_NODES  50000
#define N_EDGES  800000
#define N_GRAPHS 50
#define D        128
#define D_OUT    10

#define SCAN_B   1024
#define TM       64
#define ASTRIDE  66
#define RCHUNK   256

// ---------------- scratch (device globals: allocation-free) ----------------
__device__ int   g_indeg[N_NODES];
__device__ int   g_outdeg[N_NODES];
__device__ float g_nsrc[N_NODES];
__device__ float g_ndst[N_NODES];
__device__ int   g_rowstart[N_NODES];
__device__ int   g_cursor[N_NODES];
__device__ int   g_col[N_EDGES];
__device__ float g_colw[N_EDGES];
__device__ int   g_blksums[64];
__device__ int   g_blkoff[64];
__device__ float g_agg[N_NODES * D];
__device__ float g_xa [N_NODES * D];
__device__ float g_xb [N_NODES * D];
__device__ float g_hg [N_GRAPHS * D];
__device__ int   g_cnt[N_GRAPHS];

// ---------------- packed f32x2 helpers (sm_100+) ----------------
__device__ __forceinline__ unsigned long long pack2(float lo, float hi) {
    unsigned long long r;
    asm("mov.b64 %0, {%1, %2};" : "=l"(r) : "f"(lo), "f"(hi));
    return r;
}
__device__ __forceinline__ void unpack2(unsigned long long v, float &lo, float &hi) {
    asm("mov.b64 {%0, %1}, %2;" : "=f"(lo), "=f"(hi) : "l"(v));
}
__device__ __forceinline__ void fma2(unsigned long long &acc,
                                     unsigned long long a, unsigned long long b) {
    asm("fma.rn.f32x2 %0, %1, %2, %0;" : "+l"(acc) : "l"(a), "l"(b));
}

// ---------------- setup kernels ----------------
__global__ void k_init() {
    int i = blockIdx.x * blockDim.x + threadIdx.x;
    if (i < N_NODES) { g_indeg[i] = 0; g_outdeg[i] = 0; }
    if (i < N_GRAPHS * D) g_hg[i] = 0.0f;
    if (i < N_GRAPHS) g_cnt[i] = 0;
}

__global__ void k_deg(const int* __restrict__ src, const int* __restrict__ dst) {
    int e = blockIdx.x * blockDim.x + threadIdx.x;
    if (e < N_EDGES) {
        atomicAdd(&g_outdeg[src[e]], 1);
        atomicAdd(&g_indeg[dst[e]], 1);
    }
}

__global__ void k_norm() {
    int v = blockIdx.x * blockDim.x + threadIdx.x;
    if (v < N_NODES) {
        g_nsrc[v] = rsqrtf((float)max(g_outdeg[v], 1));
        g_ndst[v] = rsqrtf((float)max(g_indeg[v], 1));
    }
}

// two-level exclusive scan of g_indeg -> g_rowstart
__global__ void kscan1() {
    __shared__ int sm[SCAN_B];
    int i = blockIdx.x * SCAN_B + threadIdx.x;
    int v = (i < N_NODES) ? g_indeg[i] : 0;
    sm[threadIdx.x] = v;
    __syncthreads();
    for (int off = 1; off < SCAN_B; off <<= 1) {
        int t = (threadIdx.x >= off) ? sm[threadIdx.x - off] : 0;
        __syncthreads();
        sm[threadIdx.x] += t;
        __syncthreads();
    }
    if (i < N_NODES) g_rowstart[i] = sm[threadIdx.x] - v;       // exclusive (local)
    if (threadIdx.x == SCAN_B - 1) g_blksums[blockIdx.x] = sm[SCAN_B - 1];
}

__global__ void kscan2(int nb) {
    if (threadIdx.x == 0 && blockIdx.x == 0) {
        int s = 0;
        for (int i = 0; i < nb; i++) { g_blkoff[i] = s; s += g_blksums[i]; }
    }
}

__global__ void kscan3() {
    int i = blockIdx.x * SCAN_B + threadIdx.x;
    if (i < N_NODES) {
        int rs = g_rowstart[i] + g_blkoff[blockIdx.x];
        g_rowstart[i] = rs;
        g_cursor[i]   = rs;
    }
}

__global__ void k_fill(const int* __restrict__ src, const int* __restrict__ dst) {
    int e = blockIdx.x * blockDim.x + threadIdx.x;
    if (e < N_EDGES) {
        int d = dst[e];
        int p = atomicAdd(&g_cursor[d], 1);
        int s = src[e];
        g_col[p]  = s;
        g_colw[p] = g_nsrc[s];   // fold norm_src into edge weight
    }
}

// ---------------- pull-style aggregation (no fp32 atomics) ----------------
// block = one dst node, 128 threads = one feature each
__global__ void k_agg(const float* __restrict__ X) {
    __shared__ int   sc[128];
    __shared__ float sw[128];
    int v   = blockIdx.x;
    int tid = threadIdx.x;
    int beg = g_rowstart[v];
    int deg = g_indeg[v];
    float acc = 0.0f;
    for (int base = 0; base < deg; base += 128) {
        int m = min(128, deg - base);
        if (tid < m) {
            sc[tid] = g_col[beg + base + tid];
            sw[tid] = g_colw[beg + base + tid];
        }
        __syncthreads();
        int i = 0;
        for (; i + 4 <= m; i += 4) {
            float a0 = X[sc[i+0] * D + tid];
            float a1 = X[sc[i+1] * D + tid];
            float a2 = X[sc[i+2] * D + tid];
            float a3 = X[sc[i+3] * D + tid];
            acc += a0 * sw[i+0] + a1 * sw[i+1] + a2 * sw[i+2] + a3 * sw[i+3];
        }
        for (; i < m; i++) acc += X[sc[i] * D + tid] * sw[i];
        __syncthreads();
    }
    g_agg[v * D + tid] = acc * g_ndst[v];
}

// ---------------- tiled GEMM + bias + relu via packed FFMA2 ----------------
// Y[r][j] = relu( sum_k X[r][k] * W[k][j] + b[j] ), 64 rows/block, 256 threads
__global__ void k_gemm(const float* __restrict__ X, const float* __restrict__ W,
                       const float* __restrict__ b, float* __restrict__ Y, int nrows) {
    extern __shared__ float smem[];
    float* Wsm = smem;             // [128][128]
    float* Asm = smem + D * D;     // [128][ASTRIDE], transposed A tile
    int tid  = threadIdx.x;
    int row0 = blockIdx.x * TM;

    // stage W (64 KB), coalesced float4
    const float4* W4   = (const float4*)W;
    float4*       Wsm4 = (float4*)Wsm;
    for (int i = tid; i < D * D / 4; i += 256) Wsm4[i] = W4[i];

    // stage A transposed: Asm[k][r] = X[row0+r][k]   (coalesced global reads in k)
    for (int idx = tid; idx < TM * D; idx += 256) {
        int k = idx & (D - 1);
        int r = idx >> 7;
        int row = row0 + r;
        Asm[k * ASTRIDE + r] = (row < nrows) ? X[row * D + k] : 0.0f;
    }
    __syncthreads();

    int j     = tid & 127;     // output column
    int half  = tid >> 7;      // 0 -> rows 0..31, 1 -> rows 32..63
    int rbase = half * 32;

    unsigned long long acc[16];
#pragma unroll
    for (int p = 0; p < 16; p++) acc[p] = 0ULL;

#pragma unroll 2
    for (int k = 0; k < D; k++) {
        float w = Wsm[k * D + j];
        unsigned long long wp = pack2(w, w);
        const unsigned long long* arow =
            (const unsigned long long*)(Asm + k * ASTRIDE + rbase);  // 8B-aligned pairs
#pragma unroll
        for (int p = 0; p < 16; p++) fma2(acc[p], arow[p], wp);
    }

    float bj = b[j];
#pragma unroll
    for (int p = 0; p < 16; p++) {
        float lo, hi;
        unpack2(acc[p], lo, hi);
        int r = rbase + 2 * p;
        if (row0 + r     < nrows) Y[(row0 + r    ) * D + j] = fmaxf(lo + bj, 0.0f);
        if (row0 + r + 1 < nrows) Y[(row0 + r + 1) * D + j] = fmaxf(hi + bj, 0.0f);
    }
}

// ---------------- readout: sorted graph_ids -> run-length + rare atomics ----
__global__ void k_readout(const float* __restrict__ X, const int* __restrict__ gid) {
    __shared__ int sg[RCHUNK];
    int v0  = blockIdx.x * RCHUNK;
    int tid = threadIdx.x;                // 128
    int nv  = min(RCHUNK, N_NODES - v0);
    for (int i = tid; i < nv; i += 128) sg[i] = gid[v0 + i];
    __syncthreads();
    float acc = 0.0f;
    int cur = sg[0], run = 0;
    for (int i = 0; i < nv; i++) {
        int g = sg[i];
        if (g != cur) {
            atomicAdd(&g_hg[cur * D + tid], acc);
            if (tid == 0) atomicAdd(&g_cnt[cur], run);
            acc = 0.0f; run = 0; cur = g;
        }
        acc += X[(v0 + i) * D + tid];
        run++;
    }
    atomicAdd(&g_hg[cur * D + tid], acc);
    if (tid == 0) atomicAdd(&g_cnt[cur], run);
}

// ---------------- head: mean -> logits -> log_softmax over axis 0 ----------
__global__ void k_head(const float* __restrict__ Wm, const float* __restrict__ bm,
                       float* __restrict__ out) {
    __shared__ float slog[N_GRAPHS * D_OUT];
    __shared__ float lse[D_OUT];
    int tid = threadIdx.x;   // 512
    if (tid < N_GRAPHS * D_OUT) {
        int g = tid / D_OUT, j = tid % D_OUT;
        float inv = 1.0f / (float)max(g_cnt[g], 1);
        float s = bm[j];
        for (int k = 0; k < D; k++) s += g_hg[g * D + k] * inv * Wm[k * D_OUT + j];
        slog[tid] = s;
    }
    __syncthreads();
    if (tid < D_OUT) {
        float mx = -1e30f;
        for (int g = 0; g < N_GRAPHS; g++) mx = fmaxf(mx, slog[g * D_OUT + tid]);
        float s = 0.0f;
        for (int g = 0; g < N_GRAPHS; g++) s += expf(slog[g * D_OUT + tid] - mx);
        lse[tid] = mx + logf(s);
    }
    __syncthreads();
    if (tid < N_GRAPHS * D_OUT) {
        int j = tid % D_OUT;
        out[tid] = slog[tid] - lse[j];
    }
}

// ---------------- launcher ----------------
extern "C" void kernel_launch(void* const* d_in, const int* in_sizes, int n_in,
                              void* d_out, int out_size) {
    const float* h   = (const float*)d_in[0];
    const int*   src = (const int*)  d_in[1];
    const int*   dst = (const int*)  d_in[2];
    const int*   gid = (const int*)  d_in[3];
    const float* W1  = (const float*)d_in[4];
    const float* b1  = (const float*)d_in[5];
    const float* W2  = (const float*)d_in[6];
    const float* b2  = (const float*)d_in[7];
    const float* W3  = (const float*)d_in[8];
    const float* b3  = (const float*)d_in[9];
    const float* Wm  = (const float*)d_in[10];
    const float* bm  = (const float*)d_in[11];
    float*       out = (float*)d_out;

    const int smem_gemm = (D * D + D * ASTRIDE) * (int)sizeof(float);  // ~97 KB
    cudaFuncSetAttribute(k_gemm, cudaFuncAttributeMaxDynamicSharedMemorySize, smem_gemm);

    float *agg, *xa, *xb;
    cudaGetSymbolAddress((void**)&agg, g_agg);
    cudaGetSymbolAddress((void**)&xa,  g_xa);
    cudaGetSymbolAddress((void**)&xb,  g_xb);

    int nb = (N_NODES + SCAN_B - 1) / SCAN_B;

    k_init<<<(N_NODES + 255) / 256, 256>>>();
    k_deg <<<(N_EDGES + 255) / 256, 256>>>(src, dst);
    k_norm<<<(N_NODES + 255) / 256, 256>>>();
    kscan1<<<nb, SCAN_B>>>();
    kscan2<<<1, 32>>>(nb);
    kscan3<<<nb, SCAN_B>>>();
    k_fill<<<(N_EDGES + 255) / 256, 256>>>(src, dst);

    int gemm_grid = (N_NODES + TM - 1) / TM;

    k_agg <<<N_NODES, 128>>>(h);
    k_gemm<<<gemm_grid, 256, smem_gemm>>>(agg, W1, b1, xa, N_NODES);
    k_agg <<<N_NODES, 128>>>(xa);
    k_gemm<<<gemm_grid, 256, smem_gemm>>>(agg, W2, b2, xb, N_NODES);
    k_agg <<<N_NODES, 128>>>(xb);
    k_gemm<<<gemm_grid, 256, smem_gemm>>>(agg, W3, b3, xa, N_NODES);

    k_readout<<<(N_NODES + RCHUNK - 1) / RCHUNK, 128>>>(xa, gid);
    k_head<<<1, 512>>>(Wm, bm, out);
}

// round 4
// speedup vs baseline: 1.0785x; 1.0785x over previous
#include <cuda_runtime.h>
#include <math.h>

#define N_NODES  50000
#define N_EDGES  800000
#define N_GRAPHS 50
#define D        128
#define D_OUT    10

#define SCAN_B   1024
#define RCHUNK   256

#define BM 128
#define AST 130            // padded Asm row stride (even -> 8B-aligned pairs)

// ---------------- scratch (device globals: allocation-free) ----------------
__device__ int   g_indeg[N_NODES];
__device__ int   g_outdeg[N_NODES];
__device__ float g_nsrc[N_NODES];
__device__ float g_ndst[N_NODES];
__device__ int   g_rowstart[N_NODES];
__device__ int   g_cursor[N_NODES];
__device__ int   g_col[N_EDGES];
__device__ float g_colw[N_EDGES];
__device__ int   g_blksums[64];
__device__ int   g_blkoff[64];
__device__ float g_agg[N_NODES * D];
__device__ float g_xa [N_NODES * D];
__device__ float g_xb [N_NODES * D];
__device__ float g_hg [N_GRAPHS * D];
__device__ int   g_cnt[N_GRAPHS];

// ---------------- packed f32x2 helpers (sm_100+) ----------------
__device__ __forceinline__ unsigned long long pack2(float lo, float hi) {
    unsigned long long r;
    asm("mov.b64 %0, {%1, %2};" : "=l"(r) : "f"(lo), "f"(hi));
    return r;
}
__device__ __forceinline__ void unpack2(unsigned long long v, float &lo, float &hi) {
    asm("mov.b64 {%0, %1}, %2;" : "=f"(lo), "=f"(hi) : "l"(v));
}
__device__ __forceinline__ void fma2(unsigned long long &acc,
                                     unsigned long long a, unsigned long long b) {
    asm("fma.rn.f32x2 %0, %1, %2, %0;" : "+l"(acc) : "l"(a), "l"(b));
}

// ---------------- setup kernels ----------------
__global__ void k_init() {
    int i = blockIdx.x * blockDim.x + threadIdx.x;
    if (i < N_NODES) { g_indeg[i] = 0; g_outdeg[i] = 0; }
}

__global__ void k_deg(const int* __restrict__ src, const int* __restrict__ dst) {
    int e = blockIdx.x * blockDim.x + threadIdx.x;
    if (e < N_EDGES) {
        atomicAdd(&g_outdeg[src[e]], 1);
        atomicAdd(&g_indeg[dst[e]], 1);
    }
}

// two-level exclusive scan of g_indeg -> g_rowstart
__global__ void kscan1() {
    __shared__ int sm[SCAN_B];
    int i = blockIdx.x * SCAN_B + threadIdx.x;
    int v = (i < N_NODES) ? g_indeg[i] : 0;
    sm[threadIdx.x] = v;
    __syncthreads();
    for (int off = 1; off < SCAN_B; off <<= 1) {
        int t = (threadIdx.x >= off) ? sm[threadIdx.x - off] : 0;
        __syncthreads();
        sm[threadIdx.x] += t;
        __syncthreads();
    }
    if (i < N_NODES) g_rowstart[i] = sm[threadIdx.x] - v;       // exclusive (local)
    if (threadIdx.x == SCAN_B - 1) g_blksums[blockIdx.x] = sm[SCAN_B - 1];
}

__global__ void kscan2(int nb) {
    if (threadIdx.x == 0 && blockIdx.x == 0) {
        int s = 0;
        for (int i = 0; i < nb; i++) { g_blkoff[i] = s; s += g_blksums[i]; }
    }
}

// scan finalize + norms + zero readout accumulators (fused)
__global__ void kscan3() {
    int i = blockIdx.x * SCAN_B + threadIdx.x;
    if (i < N_NODES) {
        int rs = g_rowstart[i] + g_blkoff[blockIdx.x];
        g_rowstart[i] = rs;
        g_cursor[i]   = rs;
        g_nsrc[i] = rsqrtf((float)max(g_outdeg[i], 1));
        g_ndst[i] = rsqrtf((float)max(g_indeg[i], 1));
    }
    if (i < N_GRAPHS * D) g_hg[i] = 0.0f;
    if (i < N_GRAPHS) g_cnt[i] = 0;
}

__global__ void k_fill(const int* __restrict__ src, const int* __restrict__ dst) {
    int e = blockIdx.x * blockDim.x + threadIdx.x;
    if (e < N_EDGES) {
        int d = dst[e];
        int p = atomicAdd(&g_cursor[d], 1);
        int s = src[e];
        g_col[p]  = s;
        g_colw[p] = g_nsrc[s];   // fold norm_src into edge weight
    }
}

// ---------------- pull-style aggregation (no fp32 atomics) ----------------
// block = one dst node, 128 threads = one feature each  (L2-BW bound)
__global__ void k_agg(const float* __restrict__ X) {
    __shared__ int   sc[128];
    __shared__ float sw[128];
    int v   = blockIdx.x;
    int tid = threadIdx.x;
    int beg = g_rowstart[v];
    int deg = g_indeg[v];
    float acc = 0.0f;
    for (int base = 0; base < deg; base += 128) {
        int m = min(128, deg - base);
        if (tid < m) {
            sc[tid] = g_col[beg + base + tid];
            sw[tid] = g_colw[beg + base + tid];
        }
        __syncthreads();
        int i = 0;
        for (; i + 4 <= m; i += 4) {
            float a0 = X[sc[i+0] * D + tid];
            float a1 = X[sc[i+1] * D + tid];
            float a2 = X[sc[i+2] * D + tid];
            float a3 = X[sc[i+3] * D + tid];
            acc += a0 * sw[i+0] + a1 * sw[i+1] + a2 * sw[i+2] + a3 * sw[i+3];
        }
        for (; i < m; i++) acc += X[sc[i] * D + tid] * sw[i];
        __syncthreads();
    }
    g_agg[v * D + tid] = acc * g_ndst[v];
}

// ---------------- GEMM + bias + relu: 8x8 register tile, FFMA2 ------------
// Block: 256 threads, computes 128 rows x 128 cols. Thread (ty,tx) owns rows
// ty*8..+7 and cols tx*8..+7. Per k: 4 LDS.64 (A pairs) + 2 LDS.128 (W) feed
// 32 FFMA2 -> fma-pipe bound.
__global__ void __launch_bounds__(256, 1)
k_gemm(const float* __restrict__ X, const float* __restrict__ W,
       const float* __restrict__ b, float* __restrict__ Y, int nrows) {
    extern __shared__ float smem[];
    float* Wsm = smem;             // [128][128]
    float* Asm = smem + D * D;     // [128][AST], transposed A tile
    int tid  = threadIdx.x;
    int row0 = blockIdx.x * BM;

    // stage W (64 KB), coalesced float4
    const float4* W4   = (const float4*)W;
    float4*       Wsm4 = (float4*)Wsm;
    for (int i = tid; i < D * D / 4; i += 256) Wsm4[i] = W4[i];

    // stage A transposed: Asm[k][r] = X[row0+r][k]
    for (int idx = tid; idx < BM * D; idx += 256) {
        int k = idx & (D - 1);
        int r = idx >> 7;
        int row = row0 + r;
        Asm[k * AST + r] = (row < nrows) ? X[row * D + k] : 0.0f;
    }
    __syncthreads();

    int tx = tid & 15;     // col group
    int ty = tid >> 4;     // row group
    int j0 = tx * 8;
    int r0 = ty * 8;

    unsigned long long acc[4][8];
#pragma unroll
    for (int p = 0; p < 4; p++)
#pragma unroll
        for (int c = 0; c < 8; c++) acc[p][c] = 0ULL;

#pragma unroll 4
    for (int k = 0; k < D; k++) {
        const unsigned long long* ap =
            (const unsigned long long*)(Asm + k * AST + r0);
        unsigned long long a0 = ap[0], a1 = ap[1], a2 = ap[2], a3 = ap[3];
        const float* wr = Wsm + k * D + j0;
        float4 wa = *(const float4*)(wr);
        float4 wb = *(const float4*)(wr + 4);
        unsigned long long wd[8];
        wd[0] = pack2(wa.x, wa.x); wd[1] = pack2(wa.y, wa.y);
        wd[2] = pack2(wa.z, wa.z); wd[3] = pack2(wa.w, wa.w);
        wd[4] = pack2(wb.x, wb.x); wd[5] = pack2(wb.y, wb.y);
        wd[6] = pack2(wb.z, wb.z); wd[7] = pack2(wb.w, wb.w);
#pragma unroll
        for (int c = 0; c < 8; c++) {
            fma2(acc[0][c], a0, wd[c]);
            fma2(acc[1][c], a1, wd[c]);
            fma2(acc[2][c], a2, wd[c]);
            fma2(acc[3][c], a3, wd[c]);
        }
    }

    float4 bva = *(const float4*)(b + j0);
    float4 bvb = *(const float4*)(b + j0 + 4);
    float bj[8] = {bva.x, bva.y, bva.z, bva.w, bvb.x, bvb.y, bvb.z, bvb.w};

#pragma unroll
    for (int p = 0; p < 4; p++) {
        float lo[8], hi[8];
#pragma unroll
        for (int c = 0; c < 8; c++) unpack2(acc[p][c], lo[c], hi[c]);
        int rA = row0 + r0 + 2 * p;
        int rB = rA + 1;
        if (rA < nrows) {
            float4 v0 = make_float4(fmaxf(lo[0]+bj[0],0.f), fmaxf(lo[1]+bj[1],0.f),
                                    fmaxf(lo[2]+bj[2],0.f), fmaxf(lo[3]+bj[3],0.f));
            float4 v1 = make_float4(fmaxf(lo[4]+bj[4],0.f), fmaxf(lo[5]+bj[5],0.f),
                                    fmaxf(lo[6]+bj[6],0.f), fmaxf(lo[7]+bj[7],0.f));
            *(float4*)(Y + rA * D + j0)     = v0;
            *(float4*)(Y + rA * D + j0 + 4) = v1;
        }
        if (rB < nrows) {
            float4 v0 = make_float4(fmaxf(hi[0]+bj[0],0.f), fmaxf(hi[1]+bj[1],0.f),
                                    fmaxf(hi[2]+bj[2],0.f), fmaxf(hi[3]+bj[3],0.f));
            float4 v1 = make_float4(fmaxf(hi[4]+bj[4],0.f), fmaxf(hi[5]+bj[5],0.f),
                                    fmaxf(hi[6]+bj[6],0.f), fmaxf(hi[7]+bj[7],0.f));
            *(float4*)(Y + rB * D + j0)     = v0;
            *(float4*)(Y + rB * D + j0 + 4) = v1;
        }
    }
}

// ---------------- readout: sorted graph_ids -> run-length + rare atomics ----
__global__ void k_readout(const float* __restrict__ X, const int* __restrict__ gid) {
    __shared__ int sg[RCHUNK];
    int v0  = blockIdx.x * RCHUNK;
    int tid = threadIdx.x;                // 128
    int nv  = min(RCHUNK, N_NODES - v0);
    for (int i = tid; i < nv; i += 128) sg[i] = gid[v0 + i];
    __syncthreads();
    float acc = 0.0f;
    int cur = sg[0], run = 0;
    for (int i = 0; i < nv; i++) {
        int g = sg[i];
        if (g != cur) {
            atomicAdd(&g_hg[cur * D + tid], acc);
            if (tid == 0) atomicAdd(&g_cnt[cur], run);
            acc = 0.0f; run = 0; cur = g;
        }
        acc += X[(v0 + i) * D + tid];
        run++;
    }
    atomicAdd(&g_hg[cur * D + tid], acc);
    if (tid == 0) atomicAdd(&g_cnt[cur], run);
}

// ---------------- head: mean -> logits -> log_softmax over axis 0 ----------
__global__ void k_head(const float* __restrict__ Wm, const float* __restrict__ bm,
                       float* __restrict__ out) {
    __shared__ float slog[N_GRAPHS * D_OUT];
    __shared__ float lse[D_OUT];
    int tid = threadIdx.x;   // 512
    if (tid < N_GRAPHS * D_OUT) {
        int g = tid / D_OUT, j = tid % D_OUT;
        float inv = 1.0f / (float)max(g_cnt[g], 1);
        float s = bm[j];
        for (int k = 0; k < D; k++) s += g_hg[g * D + k] * inv * Wm[k * D_OUT + j];
        slog[tid] = s;
    }
    __syncthreads();
    if (tid < D_OUT) {
        float mx = -1e30f;
        for (int g = 0; g < N_GRAPHS; g++) mx = fmaxf(mx, slog[g * D_OUT + tid]);
        float s = 0.0f;
        for (int g = 0; g < N_GRAPHS; g++) s += expf(slog[g * D_OUT + tid] - mx);
        lse[tid] = mx + logf(s);
    }
    __syncthreads();
    if (tid < N_GRAPHS * D_OUT) {
        int j = tid % D_OUT;
        out[tid] = slog[tid] - lse[j];
    }
}

// ---------------- launcher ----------------
extern "C" void kernel_launch(void* const* d_in, const int* in_sizes, int n_in,
                              void* d_out, int out_size) {
    const float* h   = (const float*)d_in[0];
    const int*   src = (const int*)  d_in[1];
    const int*   dst = (const int*)  d_in[2];
    const int*   gid = (const int*)  d_in[3];
    const float* W1  = (const float*)d_in[4];
    const float* b1  = (const float*)d_in[5];
    const float* W2  = (const float*)d_in[6];
    const float* b2  = (const float*)d_in[7];
    const float* W3  = (const float*)d_in[8];
    const float* b3  = (const float*)d_in[9];
    const float* Wm  = (const float*)d_in[10];
    const float* bm  = (const float*)d_in[11];
    float*       out = (float*)d_out;

    const int smem_gemm = (D * D + D * AST) * (int)sizeof(float);  // ~129 KB
    cudaFuncSetAttribute(k_gemm, cudaFuncAttributeMaxDynamicSharedMemorySize, smem_gemm);

    float *agg, *xa, *xb;
    cudaGetSymbolAddress((void**)&agg, g_agg);
    cudaGetSymbolAddress((void**)&xa,  g_xa);
    cudaGetSymbolAddress((void**)&xb,  g_xb);

    int nb = (N_NODES + SCAN_B - 1) / SCAN_B;

    k_init<<<(N_NODES + 255) / 256, 256>>>();
    k_deg <<<(N_EDGES + 255) / 256, 256>>>(src, dst);
    kscan1<<<nb, SCAN_B>>>();
    kscan2<<<1, 32>>>(nb);
    kscan3<<<nb, SCAN_B>>>();
    k_fill<<<(N_EDGES + 255) / 256, 256>>>(src, dst);

    int gemm_grid = (N_NODES + BM - 1) / BM;

    k_agg <<<N_NODES, 128>>>(h);
    k_gemm<<<gemm_grid, 256, smem_gemm>>>(agg, W1, b1, xa, N_NODES);
    k_agg <<<N_NODES, 128>>>(xa);
    k_gemm<<<gemm_grid, 256, smem_gemm>>>(agg, W2, b2, xb, N_NODES);
    k_agg <<<N_NODES, 128>>>(xb);
    k_gemm<<<gemm_grid, 256, smem_gemm>>>(agg, W3, b3, xa, N_NODES);

    k_readout<<<(N_NODES + RCHUNK - 1) / RCHUNK, 128>>>(xa, gid);
    k_head<<<1, 512>>>(Wm, bm, out);
}

// round 5
// speedup vs baseline: 1.1764x; 1.0907x over previous
#include <cuda_runtime.h>
#include <math.h>

#define N_NODES  50000
#define N_EDGES  800000
#define N_GRAPHS 50
#define D        128
#define D_OUT    10

#define SCAN_B   1024
#define RCHUNK   256

#define BM 128
#define AST 130            // padded Asm row stride (even -> 8B-aligned pairs)

// ---------------- scratch (device globals: allocation-free) ----------------
__device__ int   g_indeg[N_NODES];
__device__ int   g_outdeg[N_NODES];
__device__ float g_nsrc[N_NODES];
__device__ float g_ndst[N_NODES];
__device__ int   g_rowstart[N_NODES];
__device__ int   g_cursor[N_NODES];
__device__ int2  g_edge[N_EDGES];        // (src_col, bitcast(norm_src))
__device__ int   g_blksums[64];
__device__ int   g_blkoff[64];
__device__ float g_agg[N_NODES * D];
__device__ float g_xa [N_NODES * D];
__device__ float g_xb [N_NODES * D];
__device__ float g_hg [N_GRAPHS * D];
__device__ int   g_cnt[N_GRAPHS];

// ---------------- packed f32x2 helpers (sm_100+) ----------------
__device__ __forceinline__ unsigned long long pack2(float lo, float hi) {
    unsigned long long r;
    asm("mov.b64 %0, {%1, %2};" : "=l"(r) : "f"(lo), "f"(hi));
    return r;
}
__device__ __forceinline__ void unpack2(unsigned long long v, float &lo, float &hi) {
    asm("mov.b64 {%0, %1}, %2;" : "=f"(lo), "=f"(hi) : "l"(v));
}
__device__ __forceinline__ void fma2(unsigned long long &acc,
                                     unsigned long long a, unsigned long long b) {
    asm("fma.rn.f32x2 %0, %1, %2, %0;" : "+l"(acc) : "l"(a), "l"(b));
}

// ---------------- setup kernels ----------------
__global__ void k_init() {
    int i = blockIdx.x * blockDim.x + threadIdx.x;
    if (i < N_NODES) { g_indeg[i] = 0; g_outdeg[i] = 0; }
}

__global__ void k_deg(const int* __restrict__ src, const int* __restrict__ dst) {
    int e = blockIdx.x * blockDim.x + threadIdx.x;
    if (e < N_EDGES) {
        atomicAdd(&g_outdeg[src[e]], 1);
        atomicAdd(&g_indeg[dst[e]], 1);
    }
}

// two-level exclusive scan of g_indeg -> g_rowstart
__global__ void kscan1() {
    __shared__ int sm[SCAN_B];
    int i = blockIdx.x * SCAN_B + threadIdx.x;
    int v = (i < N_NODES) ? g_indeg[i] : 0;
    sm[threadIdx.x] = v;
    __syncthreads();
    for (int off = 1; off < SCAN_B; off <<= 1) {
        int t = (threadIdx.x >= off) ? sm[threadIdx.x - off] : 0;
        __syncthreads();
        sm[threadIdx.x] += t;
        __syncthreads();
    }
    if (i < N_NODES) g_rowstart[i] = sm[threadIdx.x] - v;       // exclusive (local)
    if (threadIdx.x == SCAN_B - 1) g_blksums[blockIdx.x] = sm[SCAN_B - 1];
}

// parallel exclusive scan of the 49 block sums (was serial: 6.3us of L2 latency)
__global__ void kscan2(int nb) {
    __shared__ int s[64];
    int tid = threadIdx.x;            // 64 threads
    int v = (tid < nb) ? g_blksums[tid] : 0;
    s[tid] = v;
    __syncthreads();
    for (int off = 1; off < 64; off <<= 1) {
        int t = (tid >= off) ? s[tid - off] : 0;
        __syncthreads();
        s[tid] += t;
        __syncthreads();
    }
    if (tid < nb) g_blkoff[tid] = s[tid] - v;   // exclusive
}

// scan finalize + norms + zero readout accumulators (fused)
__global__ void kscan3() {
    int i = blockIdx.x * SCAN_B + threadIdx.x;
    if (i < N_NODES) {
        int rs = g_rowstart[i] + g_blkoff[blockIdx.x];
        g_rowstart[i] = rs;
        g_cursor[i]   = rs;
        g_nsrc[i] = rsqrtf((float)max(g_outdeg[i], 1));
        g_ndst[i] = rsqrtf((float)max(g_indeg[i], 1));
    }
    if (i < N_GRAPHS * D) g_hg[i] = 0.0f;
    if (i < N_GRAPHS) g_cnt[i] = 0;
}

__global__ void k_fill(const int* __restrict__ src, const int* __restrict__ dst) {
    int e = blockIdx.x * blockDim.x + threadIdx.x;
    if (e < N_EDGES) {
        int d = dst[e];
        int p = atomicAdd(&g_cursor[d], 1);
        int s = src[e];
        g_edge[p] = make_int2(s, __float_as_int(g_nsrc[s]));   // one 8B store
    }
}

// ---------------- pull-style aggregation: warp-per-edge, float4 ------------
// block = dst node; 4 warps each take every 4th edge; lane owns 4 features.
// Per edge per warp: 1 broadcast LDG.64 (edge pair) + 1 LDG.128 (row) + 4 FFMA.
__global__ void __launch_bounds__(128)
k_agg(const float* __restrict__ X) {
    __shared__ float4 red[4][32];
    int v    = blockIdx.x;
    int tid  = threadIdx.x;
    int w    = tid >> 5;
    int lane = tid & 31;
    int beg  = g_rowstart[v];
    int deg  = g_indeg[v];

    float4 acc = make_float4(0.f, 0.f, 0.f, 0.f);
    int e = w;
    // unroll by 2 edges for MLP
    for (; e + 4 < deg; e += 8) {
        int2 p0 = g_edge[beg + e];
        int2 p1 = g_edge[beg + e + 4];
        float w0 = __int_as_float(p0.y);
        float w1 = __int_as_float(p1.y);
        float4 x0 = ((const float4*)(X + (size_t)p0.x * D))[lane];
        float4 x1 = ((const float4*)(X + (size_t)p1.x * D))[lane];
        acc.x = fmaf(x0.x, w0, acc.x); acc.y = fmaf(x0.y, w0, acc.y);
        acc.z = fmaf(x0.z, w0, acc.z); acc.w = fmaf(x0.w, w0, acc.w);
        acc.x = fmaf(x1.x, w1, acc.x); acc.y = fmaf(x1.y, w1, acc.y);
        acc.z = fmaf(x1.z, w1, acc.z); acc.w = fmaf(x1.w, w1, acc.w);
    }
    for (; e < deg; e += 4) {
        int2 p0 = g_edge[beg + e];
        float w0 = __int_as_float(p0.y);
        float4 x0 = ((const float4*)(X + (size_t)p0.x * D))[lane];
        acc.x = fmaf(x0.x, w0, acc.x); acc.y = fmaf(x0.y, w0, acc.y);
        acc.z = fmaf(x0.z, w0, acc.z); acc.w = fmaf(x0.w, w0, acc.w);
    }

    red[w][lane] = acc;
    __syncthreads();
    if (w == 0) {
        float4 a = red[0][lane], b = red[1][lane],
               c = red[2][lane], d = red[3][lane];
        float nd = g_ndst[v];
        float4 o;
        o.x = (a.x + b.x + c.x + d.x) * nd;
        o.y = (a.y + b.y + c.y + d.y) * nd;
        o.z = (a.z + b.z + c.z + d.z) * nd;
        o.w = (a.w + b.w + c.w + d.w) * nd;
        ((float4*)(g_agg + (size_t)v * D))[lane] = o;
    }
}

// ---------------- GEMM + bias + relu: 8x8 register tile, FFMA2 ------------
__global__ void __launch_bounds__(256, 1)
k_gemm(const float* __restrict__ X, const float* __restrict__ W,
       const float* __restrict__ b, float* __restrict__ Y, int nrows) {
    extern __shared__ float smem[];
    float* Wsm = smem;             // [128][128]
    float* Asm = smem + D * D;     // [128][AST], transposed A tile
    int tid  = threadIdx.x;
    int row0 = blockIdx.x * BM;

    const float4* W4   = (const float4*)W;
    float4*       Wsm4 = (float4*)Wsm;
    for (int i = tid; i < D * D / 4; i += 256) Wsm4[i] = W4[i];

    for (int idx = tid; idx < BM * D; idx += 256) {
        int k = idx & (D - 1);
        int r = idx >> 7;
        int row = row0 + r;
        Asm[k * AST + r] = (row < nrows) ? X[row * D + k] : 0.0f;
    }
    __syncthreads();

    int tx = tid & 15;
    int ty = tid >> 4;
    int j0 = tx * 8;
    int r0 = ty * 8;

    unsigned long long acc[4][8];
#pragma unroll
    for (int p = 0; p < 4; p++)
#pragma unroll
        for (int c = 0; c < 8; c++) acc[p][c] = 0ULL;

#pragma unroll 4
    for (int k = 0; k < D; k++) {
        const unsigned long long* ap =
            (const unsigned long long*)(Asm + k * AST + r0);
        unsigned long long a0 = ap[0], a1 = ap[1], a2 = ap[2], a3 = ap[3];
        const float* wr = Wsm + k * D + j0;
        float4 wa = *(const float4*)(wr);
        float4 wb = *(const float4*)(wr + 4);
        unsigned long long wd[8];
        wd[0] = pack2(wa.x, wa.x); wd[1] = pack2(wa.y, wa.y);
        wd[2] = pack2(wa.z, wa.z); wd[3] = pack2(wa.w, wa.w);
        wd[4] = pack2(wb.x, wb.x); wd[5] = pack2(wb.y, wb.y);
        wd[6] = pack2(wb.z, wb.z); wd[7] = pack2(wb.w, wb.w);
#pragma unroll
        for (int c = 0; c < 8; c++) {
            fma2(acc[0][c], a0, wd[c]);
            fma2(acc[1][c], a1, wd[c]);
            fma2(acc[2][c], a2, wd[c]);
            fma2(acc[3][c], a3, wd[c]);
        }
    }

    float4 bva = *(const float4*)(b + j0);
    float4 bvb = *(const float4*)(b + j0 + 4);
    float bj[8] = {bva.x, bva.y, bva.z, bva.w, bvb.x, bvb.y, bvb.z, bvb.w};

#pragma unroll
    for (int p = 0; p < 4; p++) {
        float lo[8], hi[8];
#pragma unroll
        for (int c = 0; c < 8; c++) unpack2(acc[p][c], lo[c], hi[c]);
        int rA = row0 + r0 + 2 * p;
        int rB = rA + 1;
        if (rA < nrows) {
            float4 v0 = make_float4(fmaxf(lo[0]+bj[0],0.f), fmaxf(lo[1]+bj[1],0.f),
                                    fmaxf(lo[2]+bj[2],0.f), fmaxf(lo[3]+bj[3],0.f));
            float4 v1 = make_float4(fmaxf(lo[4]+bj[4],0.f), fmaxf(lo[5]+bj[5],0.f),
                                    fmaxf(lo[6]+bj[6],0.f), fmaxf(lo[7]+bj[7],0.f));
            *(float4*)(Y + rA * D + j0)     = v0;
            *(float4*)(Y + rA * D + j0 + 4) = v1;
        }
        if (rB < nrows) {
            float4 v0 = make_float4(fmaxf(hi[0]+bj[0],0.f), fmaxf(hi[1]+bj[1],0.f),
                                    fmaxf(hi[2]+bj[2],0.f), fmaxf(hi[3]+bj[3],0.f));
            float4 v1 = make_float4(fmaxf(hi[4]+bj[4],0.f), fmaxf(hi[5]+bj[5],0.f),
                                    fmaxf(hi[6]+bj[6],0.f), fmaxf(hi[7]+bj[7],0.f));
            *(float4*)(Y + rB * D + j0)     = v0;
            *(float4*)(Y + rB * D + j0 + 4) = v1;
        }
    }
}

// ---------------- readout: sorted graph_ids -> run-length + rare atomics ----
__global__ void k_readout(const float* __restrict__ X, const int* __restrict__ gid) {
    __shared__ int sg[RCHUNK];
    int v0  = blockIdx.x * RCHUNK;
    int tid = threadIdx.x;                // 128
    int nv  = min(RCHUNK, N_NODES - v0);
    for (int i = tid; i < nv; i += 128) sg[i] = gid[v0 + i];
    __syncthreads();
    float acc = 0.0f;
    int cur = sg[0], run = 0;
    for (int i = 0; i < nv; i++) {
        int g = sg[i];
        if (g != cur) {
            atomicAdd(&g_hg[cur * D + tid], acc);
            if (tid == 0) atomicAdd(&g_cnt[cur], run);
            acc = 0.0f; run = 0; cur = g;
        }
        acc += X[(v0 + i) * D + tid];
        run++;
    }
    atomicAdd(&g_hg[cur * D + tid], acc);
    if (tid == 0) atomicAdd(&g_cnt[cur], run);
}

// ---------------- head: mean -> logits -> log_softmax over axis 0 ----------
__global__ void k_head(const float* __restrict__ Wm, const float* __restrict__ bm,
                       float* __restrict__ out) {
    __shared__ float slog[N_GRAPHS * D_OUT];
    __shared__ float lse[D_OUT];
    int tid = threadIdx.x;   // 512
    if (tid < N_GRAPHS * D_OUT) {
        int g = tid / D_OUT, j = tid % D_OUT;
        float inv = 1.0f / (float)max(g_cnt[g], 1);
        float s = bm[j];
        for (int k = 0; k < D; k++) s += g_hg[g * D + k] * inv * Wm[k * D_OUT + j];
        slog[tid] = s;
    }
    __syncthreads();
    if (tid < D_OUT) {
        float mx = -1e30f;
        for (int g = 0; g < N_GRAPHS; g++) mx = fmaxf(mx, slog[g * D_OUT + tid]);
        float s = 0.0f;
        for (int g = 0; g < N_GRAPHS; g++) s += expf(slog[g * D_OUT + tid] - mx);
        lse[tid] = mx + logf(s);
    }
    __syncthreads();
    if (tid < N_GRAPHS * D_OUT) {
        int j = tid % D_OUT;
        out[tid] = slog[tid] - lse[j];
    }
}

// ---------------- launcher ----------------
extern "C" void kernel_launch(void* const* d_in, const int* in_sizes, int n_in,
                              void* d_out, int out_size) {
    const float* h   = (const float*)d_in[0];
    const int*   src = (const int*)  d_in[1];
    const int*   dst = (const int*)  d_in[2];
    const int*   gid = (const int*)  d_in[3];
    const float* W1  = (const float*)d_in[4];
    const float* b1  = (const float*)d_in[5];
    const float* W2  = (const float*)d_in[6];
    const float* b2  = (const float*)d_in[7];
    const float* W3  = (const float*)d_in[8];
    const float* b3  = (const float*)d_in[9];
    const float* Wm  = (const float*)d_in[10];
    const float* bm  = (const float*)d_in[11];
    float*       out = (float*)d_out;

    const int smem_gemm = (D * D + D * AST) * (int)sizeof(float);  // ~129 KB
    cudaFuncSetAttribute(k_gemm, cudaFuncAttributeMaxDynamicSharedMemorySize, smem_gemm);

    float *agg, *xa, *xb;
    cudaGetSymbolAddress((void**)&agg, g_agg);
    cudaGetSymbolAddress((void**)&xa,  g_xa);
    cudaGetSymbolAddress((void**)&xb,  g_xb);

    int nb = (N_NODES + SCAN_B - 1) / SCAN_B;

    k_init<<<(N_NODES + 255) / 256, 256>>>();
    k_deg <<<(N_EDGES + 255) / 256, 256>>>(src, dst);
    kscan1<<<nb, SCAN_B>>>();
    kscan2<<<1, 64>>>(nb);
    kscan3<<<nb, SCAN_B>>>();
    k_fill<<<(N_EDGES + 255) / 256, 256>>>(src, dst);

    int gemm_grid = (N_NODES + BM - 1) / BM;

    k_agg <<<N_NODES, 128>>>(h);
    k_gemm<<<gemm_grid, 256, smem_gemm>>>(agg, W1, b1, xa, N_NODES);
    k_agg <<<N_NODES, 128>>>(xa);
    k_gemm<<<gemm_grid, 256, smem_gemm>>>(agg, W2, b2, xb, N_NODES);
    k_agg <<<N_NODES, 128>>>(xb);
    k_gemm<<<gemm_grid, 256, smem_gemm>>>(agg, W3, b3, xa, N_NODES);

    k_readout<<<(N_NODES + RCHUNK - 1) / RCHUNK, 128>>>(xa, gid);
    k_head<<<1, 512>>>(Wm, bm, out);
}

// round 6
// speedup vs baseline: 1.2272x; 1.0432x over previous
#include <cuda_runtime.h>
#include <math.h>

#define N_NODES  50000
#define N_EDGES  800000
#define N_GRAPHS 50
#define D        128
#define D_OUT    10

#define SCAN_B   1024
#define RCHUNK   256

#define TM  64             // fused-layer row tile
#define AST 66             // padded Asm row stride (even -> 8B-aligned pairs)

// ---------------- scratch (device globals: allocation-free) ----------------
__device__ int   g_indeg[N_NODES];
__device__ int   g_outdeg[N_NODES];
__device__ float g_nsrc[N_NODES];
__device__ float g_ndst[N_NODES];
__device__ int   g_rowstart[N_NODES];
__device__ int   g_cursor[N_NODES];
__device__ int2  g_edge[N_EDGES];        // (src_col, bitcast(norm_src))
__device__ int   g_blksums[64];
__device__ int   g_blkoff[64];
__device__ float g_xa [N_NODES * D];
__device__ float g_xb [N_NODES * D];
__device__ float g_hg [N_GRAPHS * D];
__device__ int   g_cnt[N_GRAPHS];

// ---------------- packed f32x2 helpers (sm_100+) ----------------
__device__ __forceinline__ unsigned long long pack2(float lo, float hi) {
    unsigned long long r;
    asm("mov.b64 %0, {%1, %2};" : "=l"(r) : "f"(lo), "f"(hi));
    return r;
}
__device__ __forceinline__ void unpack2(unsigned long long v, float &lo, float &hi) {
    asm("mov.b64 {%0, %1}, %2;" : "=f"(lo), "=f"(hi) : "l"(v));
}
__device__ __forceinline__ void fma2(unsigned long long &acc,
                                     unsigned long long a, unsigned long long b) {
    asm("fma.rn.f32x2 %0, %1, %2, %0;" : "+l"(acc) : "l"(a), "l"(b));
}

// ---------------- setup kernels ----------------
__global__ void k_init() {
    int i = blockIdx.x * blockDim.x + threadIdx.x;
    if (i < N_NODES) { g_indeg[i] = 0; g_outdeg[i] = 0; }
}

__global__ void k_deg(const int* __restrict__ src, const int* __restrict__ dst) {
    int e = blockIdx.x * blockDim.x + threadIdx.x;
    if (e < N_EDGES) {
        atomicAdd(&g_outdeg[src[e]], 1);
        atomicAdd(&g_indeg[dst[e]], 1);
    }
}

// two-level exclusive scan of g_indeg -> g_rowstart
__global__ void kscan1() {
    __shared__ int sm[SCAN_B];
    int i = blockIdx.x * SCAN_B + threadIdx.x;
    int v = (i < N_NODES) ? g_indeg[i] : 0;
    sm[threadIdx.x] = v;
    __syncthreads();
    for (int off = 1; off < SCAN_B; off <<= 1) {
        int t = (threadIdx.x >= off) ? sm[threadIdx.x - off] : 0;
        __syncthreads();
        sm[threadIdx.x] += t;
        __syncthreads();
    }
    if (i < N_NODES) g_rowstart[i] = sm[threadIdx.x] - v;       // exclusive (local)
    if (threadIdx.x == SCAN_B - 1) g_blksums[blockIdx.x] = sm[SCAN_B - 1];
}

__global__ void kscan2(int nb) {
    __shared__ int s[64];
    int tid = threadIdx.x;            // 64 threads
    int v = (tid < nb) ? g_blksums[tid] : 0;
    s[tid] = v;
    __syncthreads();
    for (int off = 1; off < 64; off <<= 1) {
        int t = (tid >= off) ? s[tid - off] : 0;
        __syncthreads();
        s[tid] += t;
        __syncthreads();
    }
    if (tid < nb) g_blkoff[tid] = s[tid] - v;   // exclusive
}

// scan finalize + norms + zero readout accumulators (fused)
__global__ void kscan3() {
    int i = blockIdx.x * SCAN_B + threadIdx.x;
    if (i < N_NODES) {
        int rs = g_rowstart[i] + g_blkoff[blockIdx.x];
        g_rowstart[i] = rs;
        g_cursor[i]   = rs;
        g_nsrc[i] = rsqrtf((float)max(g_outdeg[i], 1));
        g_ndst[i] = rsqrtf((float)max(g_indeg[i], 1));
    }
    if (i < N_GRAPHS * D) g_hg[i] = 0.0f;
    if (i < N_GRAPHS) g_cnt[i] = 0;
}

__global__ void k_fill(const int* __restrict__ src, const int* __restrict__ dst) {
    int e = blockIdx.x * blockDim.x + threadIdx.x;
    if (e < N_EDGES) {
        int d = dst[e];
        int p = atomicAdd(&g_cursor[d], 1);
        int s = src[e];
        g_edge[p] = make_int2(s, __float_as_int(g_nsrc[s]));   // one 8B store
    }
}

// ---------------- fused layer: pull-agg (smem) + GEMM + bias + relu --------
// Block = 64 dst nodes, 256 threads, 2 CTAs/SM (phase overlap across CTAs).
// Phase 1: warp w aggregates nodes w*8..w*8+7; lane owns a float4 feature
//          chunk; result written transposed into Asm, pre-scaled by ndst.
// Phase 2: 64x128 GEMM from smem, 4x8 register tile per thread via FFMA2.
__global__ void __launch_bounds__(256, 2)
k_layer(const float* __restrict__ X, const float* __restrict__ W,
        const float* __restrict__ b, float* __restrict__ Y, int nrows) {
    extern __shared__ float smem[];
    float* Wsm = smem;             // [128][128]
    float* Asm = smem + D * D;     // [128][AST] transposed agg tile
    int tid  = threadIdx.x;
    int w    = tid >> 5;
    int lane = tid & 31;
    int row0 = blockIdx.x * TM;

    // stage W (64 KB) — independent of agg, overlaps with it
    {
        const float4* W4   = (const float4*)W;
        float4*       Wsm4 = (float4*)Wsm;
#pragma unroll
        for (int i = 0; i < D * D / 4 / 256; i++)
            Wsm4[tid + i * 256] = W4[tid + i * 256];
    }

    // Phase 1: aggregation, 8 nodes per warp, all in registers
#pragma unroll
    for (int n = 0; n < 8; n++) {
        int r = w * 8 + n;
        int v = row0 + r;
        float4 acc = make_float4(0.f, 0.f, 0.f, 0.f);
        if (v < nrows) {
            int beg = g_rowstart[v];
            int deg = g_indeg[v];
            int e = 0;
            for (; e + 4 <= deg; e += 4) {        // 4 edges in flight
                int2 p0 = g_edge[beg + e + 0];
                int2 p1 = g_edge[beg + e + 1];
                int2 p2 = g_edge[beg + e + 2];
                int2 p3 = g_edge[beg + e + 3];
                float4 x0 = ((const float4*)(X + (size_t)p0.x * D))[lane];
                float4 x1 = ((const float4*)(X + (size_t)p1.x * D))[lane];
                float4 x2 = ((const float4*)(X + (size_t)p2.x * D))[lane];
                float4 x3 = ((const float4*)(X + (size_t)p3.x * D))[lane];
                float w0 = __int_as_float(p0.y), w1 = __int_as_float(p1.y);
                float w2 = __int_as_float(p2.y), w3 = __int_as_float(p3.y);
                acc.x = fmaf(x0.x, w0, acc.x); acc.y = fmaf(x0.y, w0, acc.y);
                acc.z = fmaf(x0.z, w0, acc.z); acc.w = fmaf(x0.w, w0, acc.w);
                acc.x = fmaf(x1.x, w1, acc.x); acc.y = fmaf(x1.y, w1, acc.y);
                acc.z = fmaf(x1.z, w1, acc.z); acc.w = fmaf(x1.w, w1, acc.w);
                acc.x = fmaf(x2.x, w2, acc.x); acc.y = fmaf(x2.y, w2, acc.y);
                acc.z = fmaf(x2.z, w2, acc.z); acc.w = fmaf(x2.w, w2, acc.w);
                acc.x = fmaf(x3.x, w3, acc.x); acc.y = fmaf(x3.y, w3, acc.y);
                acc.z = fmaf(x3.z, w3, acc.z); acc.w = fmaf(x3.w, w3, acc.w);
            }
            for (; e < deg; e++) {
                int2 p0 = g_edge[beg + e];
                float w0 = __int_as_float(p0.y);
                float4 x0 = ((const float4*)(X + (size_t)p0.x * D))[lane];
                acc.x = fmaf(x0.x, w0, acc.x); acc.y = fmaf(x0.y, w0, acc.y);
                acc.z = fmaf(x0.z, w0, acc.z); acc.w = fmaf(x0.w, w0, acc.w);
            }
            float nd = g_ndst[v];
            acc.x *= nd; acc.y *= nd; acc.z *= nd; acc.w *= nd;
        }
        // transposed store (pre-scaled); zeros for invalid rows
        float* ap = Asm + r;
        ap[(4 * lane + 0) * AST] = acc.x;
        ap[(4 * lane + 1) * AST] = acc.y;
        ap[(4 * lane + 2) * AST] = acc.z;
        ap[(4 * lane + 3) * AST] = acc.w;
    }
    __syncthreads();

    // Phase 2: GEMM 64x128, thread = 4 rows x 8 cols
    int tx = tid & 15;     // col group
    int ty = tid >> 4;     // row group
    int j0 = tx * 8;
    int r0 = ty * 4;

    unsigned long long acc[2][8];
#pragma unroll
    for (int p = 0; p < 2; p++)
#pragma unroll
        for (int c = 0; c < 8; c++) acc[p][c] = 0ULL;

#pragma unroll 4
    for (int k = 0; k < D; k++) {
        const unsigned long long* ap =
            (const unsigned long long*)(Asm + k * AST + r0);
        unsigned long long a0 = ap[0], a1 = ap[1];
        const float* wr = Wsm + k * D + j0;
        float4 wa = *(const float4*)(wr);
        float4 wb = *(const float4*)(wr + 4);
        unsigned long long wd[8];
        wd[0] = pack2(wa.x, wa.x); wd[1] = pack2(wa.y, wa.y);
        wd[2] = pack2(wa.z, wa.z); wd[3] = pack2(wa.w, wa.w);
        wd[4] = pack2(wb.x, wb.x); wd[5] = pack2(wb.y, wb.y);
        wd[6] = pack2(wb.z, wb.z); wd[7] = pack2(wb.w, wb.w);
#pragma unroll
        for (int c = 0; c < 8; c++) {
            fma2(acc[0][c], a0, wd[c]);
            fma2(acc[1][c], a1, wd[c]);
        }
    }

    float4 bva = *(const float4*)(b + j0);
    float4 bvb = *(const float4*)(b + j0 + 4);
    float bj[8] = {bva.x, bva.y, bva.z, bva.w, bvb.x, bvb.y, bvb.z, bvb.w};

#pragma unroll
    for (int p = 0; p < 2; p++) {
        float lo[8], hi[8];
#pragma unroll
        for (int c = 0; c < 8; c++) unpack2(acc[p][c], lo[c], hi[c]);
        int rA = row0 + r0 + 2 * p;
        int rB = rA + 1;
        if (rA < nrows) {
            float4 v0 = make_float4(fmaxf(lo[0]+bj[0],0.f), fmaxf(lo[1]+bj[1],0.f),
                                    fmaxf(lo[2]+bj[2],0.f), fmaxf(lo[3]+bj[3],0.f));
            float4 v1 = make_float4(fmaxf(lo[4]+bj[4],0.f), fmaxf(lo[5]+bj[5],0.f),
                                    fmaxf(lo[6]+bj[6],0.f), fmaxf(lo[7]+bj[7],0.f));
            *(float4*)(Y + rA * D + j0)     = v0;
            *(float4*)(Y + rA * D + j0 + 4) = v1;
        }
        if (rB < nrows) {
            float4 v0 = make_float4(fmaxf(hi[0]+bj[0],0.f), fmaxf(hi[1]+bj[1],0.f),
                                    fmaxf(hi[2]+bj[2],0.f), fmaxf(hi[3]+bj[3],0.f));
            float4 v1 = make_float4(fmaxf(hi[4]+bj[4],0.f), fmaxf(hi[5]+bj[5],0.f),
                                    fmaxf(hi[6]+bj[6],0.f), fmaxf(hi[7]+bj[7],0.f));
            *(float4*)(Y + rB * D + j0)     = v0;
            *(float4*)(Y + rB * D + j0 + 4) = v1;
        }
    }
}

// ---------------- readout: sorted graph_ids -> run-length + rare atomics ----
__global__ void k_readout(const float* __restrict__ X, const int* __restrict__ gid) {
    __shared__ int sg[RCHUNK];
    int v0  = blockIdx.x * RCHUNK;
    int tid = threadIdx.x;                // 128
    int nv  = min(RCHUNK, N_NODES - v0);
    for (int i = tid; i < nv; i += 128) sg[i] = gid[v0 + i];
    __syncthreads();
    float acc = 0.0f;
    int cur = sg[0], run = 0;
    for (int i = 0; i < nv; i++) {
        int g = sg[i];
        if (g != cur) {
            atomicAdd(&g_hg[cur * D + tid], acc);
            if (tid == 0) atomicAdd(&g_cnt[cur], run);
            acc = 0.0f; run = 0; cur = g;
        }
        acc += X[(v0 + i) * D + tid];
        run++;
    }
    atomicAdd(&g_hg[cur * D + tid], acc);
    if (tid == 0) atomicAdd(&g_cnt[cur], run);
}

// ---------------- head: mean -> logits -> log_softmax over axis 0 ----------
__global__ void k_head(const float* __restrict__ Wm, const float* __restrict__ bm,
                       float* __restrict__ out) {
    __shared__ float slog[N_GRAPHS * D_OUT];
    __shared__ float lse[D_OUT];
    int tid = threadIdx.x;   // 512
    if (tid < N_GRAPHS * D_OUT) {
        int g = tid / D_OUT, j = tid % D_OUT;
        float inv = 1.0f / (float)max(g_cnt[g], 1);
        float s = bm[j];
        for (int k = 0; k < D; k++) s += g_hg[g * D + k] * inv * Wm[k * D_OUT + j];
        slog[tid] = s;
    }
    __syncthreads();
    if (tid < D_OUT) {
        float mx = -1e30f;
        for (int g = 0; g < N_GRAPHS; g++) mx = fmaxf(mx, slog[g * D_OUT + tid]);
        float s = 0.0f;
        for (int g = 0; g < N_GRAPHS; g++) s += expf(slog[g * D_OUT + tid] - mx);
        lse[tid] = mx + logf(s);
    }
    __syncthreads();
    if (tid < N_GRAPHS * D_OUT) {
        int j = tid % D_OUT;
        out[tid] = slog[tid] - lse[j];
    }
}

// ---------------- launcher ----------------
extern "C" void kernel_launch(void* const* d_in, const int* in_sizes, int n_in,
                              void* d_out, int out_size) {
    const float* h   = (const float*)d_in[0];
    const int*   src = (const int*)  d_in[1];
    const int*   dst = (const int*)  d_in[2];
    const int*   gid = (const int*)  d_in[3];
    const float* W1  = (const float*)d_in[4];
    const float* b1  = (const float*)d_in[5];
    const float* W2  = (const float*)d_in[6];
    const float* b2  = (const float*)d_in[7];
    const float* W3  = (const float*)d_in[8];
    const float* b3  = (const float*)d_in[9];
    const float* Wm  = (const float*)d_in[10];
    const float* bm  = (const float*)d_in[11];
    float*       out = (float*)d_out;

    const int smem_layer = (D * D + D * AST) * (int)sizeof(float);  // ~97 KB
    cudaFuncSetAttribute(k_layer, cudaFuncAttributeMaxDynamicSharedMemorySize, smem_layer);

    float *xa, *xb;
    cudaGetSymbolAddress((void**)&xa, g_xa);
    cudaGetSymbolAddress((void**)&xb, g_xb);

    int nb = (N_NODES + SCAN_B - 1) / SCAN_B;

    k_init<<<(N_NODES + 255) / 256, 256>>>();
    k_deg <<<(N_EDGES + 255) / 256, 256>>>(src, dst);
    kscan1<<<nb, SCAN_B>>>();
    kscan2<<<1, 64>>>(nb);
    kscan3<<<nb, SCAN_B>>>();
    k_fill<<<(N_EDGES + 255) / 256, 256>>>(src, dst);

    int grid = (N_NODES + TM - 1) / TM;   // 782

    k_layer<<<grid, 256, smem_layer>>>(h,  W1, b1, xa, N_NODES);
    k_layer<<<grid, 256, smem_layer>>>(xa, W2, b2, xb, N_NODES);
    k_layer<<<grid, 256, smem_layer>>>(xb, W3, b3, xa, N_NODES);

    k_readout<<<(N_NODES + RCHUNK - 1) / RCHUNK, 128>>>(xa, gid);
    k_head<<<1, 512>>>(Wm, bm, out);
}